// round 3
// baseline (speedup 1.0000x reference)
#include <cuda_runtime.h>

// 4M-step sequential sigmoid recurrence, parallelized by saturation-collapse
// chunking, with shared-memory transpose staging for coalesced global access.
// Ladder: per-chunk fail flag -> fixup (HW2 warmup) -> full serial fallback.

#define LCH   256                 // steps per chunk
#define HW    64                  // warmup steps
#define HW2   512                 // fixup warmup
#define TPB   128                 // threads (=chunks) per block
#define TSTEP 16                  // steps per smem tile
#define NTW   (HW / TSTEP)        // 4 warmup tiles
#define NTT   ((HW + LCH) / TSTEP)// 20 total tiles
#define SEGP  (TPB + 1)           // padded seg stride (odd -> conflict free)
#define CL    (-14.42695040888963f)  // -10 * log2(e)

__device__ unsigned char g_chunk_fail[65536];
__device__ int g_fail2;

__device__ __forceinline__ float ex2a(float t){ float r; asm("ex2.approx.ftz.f32 %0, %1;" : "=f"(r) : "f"(t)); return r; }
__device__ __forceinline__ float rcpa(float t){ float r; asm("rcp.approx.ftz.f32 %0, %1;" : "=f"(r) : "f"(t)); return r; }
__device__ __forceinline__ float sg(float n, float v){ return rcpa(1.0f + ex2a(fmaf(CL, n, v))); }

#define MAKEV(x0,x1,x2) \
    float v0 = fmaf(cw00,(x0), fmaf(cw01,(x1), fmaf(cw02,(x2), cb0))); \
    float v1 = fmaf(cw10,(x0), fmaf(cw11,(x1), fmaf(cw12,(x2), cb1))); \
    float v2 = fmaf(cw20,(x0), fmaf(cw21,(x1), fmaf(cw22,(x2), cb2)));

#define LOADW \
    const float cb0 = CL*(__ldg(b+0)-0.5f), cb1 = CL*(__ldg(b+1)-0.5f), cb2 = CL*(__ldg(b+2)-0.5f); \
    const float cw00=CL*__ldg(W+0), cw01=CL*__ldg(W+1), cw02=CL*__ldg(W+2); \
    const float cw10=CL*__ldg(W+3), cw11=CL*__ldg(W+4), cw12=CL*__ldg(W+5); \
    const float cw20=CL*__ldg(W+6), cw21=CL*__ldg(W+7), cw22=CL*__ldg(W+8);

extern __shared__ float smem_dyn[];

__global__ void __launch_bounds__(TPB)
scan_chunks(const float* __restrict__ x, const float* __restrict__ W,
            const float* __restrict__ b, const float* __restrict__ net0,
            float* __restrict__ out)
{
    float* xb[2] = { smem_dyn, smem_dyn + 3*TSTEP*SEGP };
    float* pb[2] = { smem_dyn + 6*TSTEP*SEGP, smem_dyn + 6*TSTEP*SEGP + TSTEP*SEGP };

    const int tid  = threadIdx.x;
    const int w    = tid >> 5;
    const int lane = tid & 31;
    const long cbase = (long)blockIdx.x * TPB;
    const long c = cbase + tid;
    if (c == 0) g_fail2 = 0;

    LOADW

    // ---- staging: warp w loads segments [w*32, w*32+32), transposed store ----
    auto stage = [&](int t, float* dst){
        long base = cbase*(3L*LCH) - 3L*HW + (long)t*(3*TSTEP);
        long gi = base + (long)(w*32)*(3*LCH);
        #pragma unroll 4
        for (int s2 = 0; s2 < 32; ++s2) {
            int seg = w*32 + s2;
            long i0 = gi + lane;
            float v0 = (i0 >= 0) ? __ldg(x + i0) : 0.0f;   // guard only bites for chunk 0 warmup
            dst[lane*SEGP + seg] = v0;
            if (lane < 16) {
                long i1 = gi + 32 + lane;
                float v1 = (i1 >= 0) ? __ldg(x + i1) : 0.0f;
                dst[(32+lane)*SEGP + seg] = v1;
            }
            gi += 3*LCH;
        }
    };

    float lo0=0.f, lo1=0.f, lo2=0.f, hi0=1.f, hi1=1.f, hi2=1.f;
    float n0=0.f, n1=0.f, n2=0.f;
    bool col = false;
    unsigned char fail = 0;

    stage(0, xb[0]);
    __syncthreads();

    for (int t = 0; t < NTT; ++t) {
        float* xc = xb[t & 1];
        float* pc = pb[t & 1];
        if (t + 1 < NTT) stage(t + 1, xb[(t + 1) & 1]);

        if (t < NTW) {
            // ---- warmup tile: two-state until bitwise collapse, then one-state ----
            if (!col) {
                #pragma unroll
                for (int s = 0; s < TSTEP; ++s) {
                    float x0 = xc[(3*s  )*SEGP + tid];
                    float x1 = xc[(3*s+1)*SEGP + tid];
                    float x2 = xc[(3*s+2)*SEGP + tid];
                    MAKEV(x0,x1,x2)
                    lo0=sg(lo0,v0); lo1=sg(lo1,v1); lo2=sg(lo2,v2);
                    hi0=sg(hi0,v0); hi1=sg(hi1,v1); hi2=sg(hi2,v2);
                }
                col = (lo0==hi0) && (lo1==hi1) && (lo2==hi2);
            } else {
                #pragma unroll
                for (int s = 0; s < TSTEP; ++s) {
                    float x0 = xc[(3*s  )*SEGP + tid];
                    float x1 = xc[(3*s+1)*SEGP + tid];
                    float x2 = xc[(3*s+2)*SEGP + tid];
                    MAKEV(x0,x1,x2)
                    lo0=sg(lo0,v0); lo1=sg(lo1,v1); lo2=sg(lo2,v2);
                }
            }
            if (t == NTW-1) {
                if (!col) fail = 1;
                n0 = lo0; n1 = lo1; n2 = lo2;
                if (c == 0) {       // chunk 0: exact initial state, warmup discarded
                    n0 = __ldg(net0+0); n1 = __ldg(net0+1); n2 = __ldg(net0+2);
                    fail = 0;
                }
            }
        } else {
            // ---- main tile: 16 steps, preds into transposed smem ----
            #pragma unroll
            for (int s = 0; s < TSTEP; ++s) {
                float x0 = xc[(3*s  )*SEGP + tid];
                float x1 = xc[(3*s+1)*SEGP + tid];
                float x2 = xc[(3*s+2)*SEGP + tid];
                MAKEV(x0,x1,x2)
                n0=sg(n0,v0); n1=sg(n1,v1); n2=sg(n2,v2);
                pc[s*SEGP + tid] = fmaf(x0,n0, fmaf(x1,n1, x2*n2));
            }
        }

        __syncthreads();   // staged tile visible; preds visible; safe buffer rotation

        if (t >= NTW) {
            // ---- cooperative coalesced output: warp w covers its 32 segments ----
            int half = lane >> 4;
            int e    = lane & 15;
            long obase = cbase*LCH + (long)(t - NTW)*TSTEP + e;
            #pragma unroll 4
            for (int s2 = 0; s2 < 32; s2 += 2) {
                int seg = w*32 + s2 + half;
                out[obase + (long)seg*LCH] = pc[e*SEGP + seg];
            }
        }
    }

    g_chunk_fail[c] = fail;
}

// Rare path: chunks that failed to collapse redo with HW2 warmup.
__global__ void fixup_kernel(const float* __restrict__ x, const float* __restrict__ W,
                             const float* __restrict__ b, const float* __restrict__ net0,
                             float* __restrict__ out, int nchunk)
{
    int c = blockIdx.x * blockDim.x + threadIdx.x;
    if (c >= nchunk) return;
    if (!g_chunk_fail[c]) return;
    long start = (long)c * LCH;

    LOADW
    long hw = start < HW2 ? start : HW2;
    const float* xp = x + 3*(start - hw);
    float lo0=0.f,lo1=0.f,lo2=0.f,hi0=1.f,hi1=1.f,hi2=1.f;
    bool col = false;
    for (long s = 0; s < hw; ++s) {
        float x0=xp[0], x1=xp[1], x2=xp[2]; xp += 3;
        MAKEV(x0,x1,x2)
        lo0=sg(lo0,v0); lo1=sg(lo1,v1); lo2=sg(lo2,v2);
        if (!col) {
            hi0=sg(hi0,v0); hi1=sg(hi1,v1); hi2=sg(hi2,v2);
            col = (lo0==hi0)&&(lo1==hi1)&&(lo2==hi2);
        }
    }
    if (!col && start > 0) atomicOr(&g_fail2, 1);
    float n0=lo0, n1=lo1, n2=lo2;
    if (start == 0) { n0=__ldg(net0+0); n1=__ldg(net0+1); n2=__ldg(net0+2); }
    for (int j = 0; j < LCH; ++j) {
        float x0=xp[0], x1=xp[1], x2=xp[2]; xp += 3;
        MAKEV(x0,x1,x2)
        n0=sg(n0,v0); n1=sg(n1,v1); n2=sg(n2,v2);
        out[start + j] = fmaf(x0,n0, fmaf(x1,n1, x2*n2));
    }
}

// Generic tail (leftover chunks / partial chunk) — not launched for B=4M.
__global__ void edge_kernel(const float* __restrict__ x, const float* __restrict__ W,
                            const float* __restrict__ b, const float* __restrict__ net0,
                            float* __restrict__ out, long firstStep, int nB)
{
    long idx = blockIdx.x * blockDim.x + threadIdx.x;
    long start = firstStep + idx * LCH;
    if (start >= nB) return;
    LOADW
    long hw = start < HW2 ? start : HW2;
    const float* xp = x + 3*(start - hw);
    float lo0=0.f,lo1=0.f,lo2=0.f,hi0=1.f,hi1=1.f,hi2=1.f;
    bool col = false;
    for (long s = 0; s < hw; ++s) {
        float x0=xp[0], x1=xp[1], x2=xp[2]; xp += 3;
        MAKEV(x0,x1,x2)
        lo0=sg(lo0,v0); lo1=sg(lo1,v1); lo2=sg(lo2,v2);
        if (!col) {
            hi0=sg(hi0,v0); hi1=sg(hi1,v1); hi2=sg(hi2,v2);
            col = (lo0==hi0)&&(lo1==hi1)&&(lo2==hi2);
        }
    }
    if (!col && start > 0) atomicOr(&g_fail2, 1);
    float n0=lo0, n1=lo1, n2=lo2;
    if (start == 0) { n0=__ldg(net0+0); n1=__ldg(net0+1); n2=__ldg(net0+2); }
    long L = (start + LCH <= nB) ? LCH : (nB - start);
    for (long j = 0; j < L; ++j) {
        float x0=xp[0], x1=xp[1], x2=xp[2]; xp += 3;
        MAKEV(x0,x1,x2)
        n0=sg(n0,v0); n1=sg(n1,v1); n2=sg(n2,v2);
        out[start + j] = fmaf(x0,n0, fmaf(x1,n1, x2*n2));
    }
}

// Ultimate fallback: full serial scan (only if fixup/edge failed to collapse).
__global__ void fallback_kernel(const float* __restrict__ x, const float* __restrict__ W,
                                const float* __restrict__ b, const float* __restrict__ net0,
                                float* __restrict__ out, int nB)
{
    if (g_fail2 == 0) return;
    if (threadIdx.x != 0 || blockIdx.x != 0) return;
    LOADW
    float n0=__ldg(net0+0), n1=__ldg(net0+1), n2=__ldg(net0+2);
    const float* xp = x;
    for (int i = 0; i < nB; ++i) {
        float x0=xp[0], x1=xp[1], x2=xp[2]; xp += 3;
        MAKEV(x0,x1,x2)
        n0=sg(n0,v0); n1=sg(n1,v1); n2=sg(n2,v2);
        out[i] = fmaf(x0,n0, fmaf(x1,n1, x2*n2));
    }
}

extern "C" void kernel_launch(void* const* d_in, const int* in_sizes, int n_in,
                              void* d_out, int out_size)
{
    const float *x = 0, *W = 0, *b = 0, *n0p = 0;
    long nB = out_size;
    for (int i = 0; i < n_in; ++i) {
        long sz = in_sizes[i];
        if (sz == 3 * nB)      x = (const float*)d_in[i];
        else if (sz == 9)      W = (const float*)d_in[i];
        else if (sz == 3) {
            if (!b) b = (const float*)d_in[i];
            else    n0p = (const float*)d_in[i];
        }
    }
    float* out = (float*)d_out;

    long nchunkFull = nB / LCH;                    // full chunks
    long blocks     = nchunkFull / TPB;            // full blocks for the scan
    long nscan      = blocks * TPB;                // chunks covered by scan
    long firstEdge  = nscan * LCH;                 // first step not covered

    size_t smem = (size_t)(6*TSTEP*SEGP + 2*TSTEP*SEGP) * sizeof(float); // ~66KB
    static int attr_done = 0;
    if (!attr_done) {
        cudaFuncSetAttribute(scan_chunks, cudaFuncAttributeMaxDynamicSharedMemorySize, (int)smem);
        attr_done = 1;
    }

    if (blocks > 0)
        scan_chunks<<<(int)blocks, TPB, smem>>>(x, W, b, n0p, out);
    if (nscan > 0)
        fixup_kernel<<<(int)((nscan + 127)/128), 128>>>(x, W, b, n0p, out, (int)nscan);
    if (firstEdge < nB) {
        long nEdge = (nB - firstEdge + LCH - 1) / LCH;
        edge_kernel<<<(int)((nEdge + 127)/128), 128>>>(x, W, b, n0p, out, firstEdge, (int)nB);
    }
    fallback_kernel<<<1, 1>>>(x, W, b, n0p, out, (int)nB);
}

// round 5
// speedup vs baseline: 3.7712x; 3.7712x over previous
#include <cuda_runtime.h>

// 4M-step sequential sigmoid recurrence, parallelized by saturation-collapse
// chunking. Per-thread float4 double-buffered streaming; 65536 threads for
// latency hiding. Ladder: per-chunk fail flag -> fixup (HW2 warmup) -> serial.

#define LCH 64             // steps per chunk (multiple of 8)
#define HW  48             // warmup steps (multiple of 8, 16B-aligned offset)
#define HW2 512            // fixup warmup
#define TPB 256
#define CL (-14.42695040888963f)   // -10 * log2(e)

__device__ unsigned char g_chunk_fail[65536];
__device__ int g_fail2;

__device__ __forceinline__ float ex2a(float t){ float r; asm("ex2.approx.ftz.f32 %0, %1;" : "=f"(r) : "f"(t)); return r; }
__device__ __forceinline__ float rcpa(float t){ float r; asm("rcp.approx.ftz.f32 %0, %1;" : "=f"(r) : "f"(t)); return r; }
__device__ __forceinline__ float sg(float n, float v){ return rcpa(1.0f + ex2a(fmaf(CL, n, v))); }

#define MAKEV(x0,x1,x2) \
    float v0 = fmaf(cw00,(x0), fmaf(cw01,(x1), fmaf(cw02,(x2), cb0))); \
    float v1 = fmaf(cw10,(x0), fmaf(cw11,(x1), fmaf(cw12,(x2), cb1))); \
    float v2 = fmaf(cw20,(x0), fmaf(cw21,(x1), fmaf(cw22,(x2), cb2)));

#define LOADW \
    const float cb0 = CL*(__ldg(b+0)-0.5f), cb1 = CL*(__ldg(b+1)-0.5f), cb2 = CL*(__ldg(b+2)-0.5f); \
    const float cw00=CL*__ldg(W+0), cw01=CL*__ldg(W+1), cw02=CL*__ldg(W+2); \
    const float cw10=CL*__ldg(W+3), cw11=CL*__ldg(W+4), cw12=CL*__ldg(W+5); \
    const float cw20=CL*__ldg(W+6), cw21=CL*__ldg(W+7), cw22=CL*__ldg(W+8);

#define TWOSTEP(x0,x1,x2) do { \
    MAKEV(x0,x1,x2) \
    lo0=sg(lo0,v0); lo1=sg(lo1,v1); lo2=sg(lo2,v2); \
    hi0=sg(hi0,v0); hi1=sg(hi1,v1); hi2=sg(hi2,v2); } while(0)

#define ONESTEPW(x0,x1,x2) do { \
    MAKEV(x0,x1,x2) \
    lo0=sg(lo0,v0); lo1=sg(lo1,v1); lo2=sg(lo2,v2); } while(0)

#define MAINSTEP(x0,x1,x2,pd) do { \
    MAKEV(x0,x1,x2) \
    n0=sg(n0,v0); n1=sg(n1,v1); n2=sg(n2,v2); \
    pd = fmaf((x0),n0, fmaf((x1),n1, (x2)*n2)); } while(0)

#define BLOCK8(OP) do { \
    OP(c0.x,c0.y,c0.z,0); OP(c0.w,c1.x,c1.y,1); \
    OP(c1.z,c1.w,c2.x,2); OP(c2.y,c2.z,c2.w,3); \
    OP(c3.x,c3.y,c3.z,4); OP(c3.w,c4.x,c4.y,5); \
    OP(c4.z,c4.w,c5.x,6); OP(c5.y,c5.z,c5.w,7); } while(0)

#define OP_TWO(x0,x1,x2,j)  TWOSTEP(x0,x1,x2)
#define OP_ONE(x0,x1,x2,j)  ONESTEPW(x0,x1,x2)
#define OP_MAIN(x0,x1,x2,j) MAINSTEP(x0,x1,x2,p##j)

#define LOAD6(n0_,n1_,n2_,n3_,n4_,n5_,base) do { \
    n0_=__ldg((base)+0); n1_=__ldg((base)+1); n2_=__ldg((base)+2); \
    n3_=__ldg((base)+3); n4_=__ldg((base)+4); n5_=__ldg((base)+5); } while(0)

__global__ void __launch_bounds__(TPB)
scan_chunks(const float* __restrict__ x, const float* __restrict__ W,
            const float* __restrict__ b, const float* __restrict__ net0,
            float* __restrict__ out, int nchunk, int nB)
{
    int c = blockIdx.x * TPB + threadIdx.x;
    if (c == 0) g_fail2 = 0;
    if (c >= nchunk) return;
    long start = (long)c * LCH;

    LOADW

    float n0, n1, n2;
    unsigned char fail = 0;

    if (c == 0) {
        n0=__ldg(net0+0); n1=__ldg(net0+1); n2=__ldg(net0+2);
    } else {
        // Warmup from start-HW with interval bounds [0,1]. 3*HW floats = 16B aligned.
        const float4* xv = (const float4*)(x + 3*(start - HW));
        float lo0=0.f, lo1=0.f, lo2=0.f, hi0=1.f, hi1=1.f, hi2=1.f;
        float4 c0,c1,c2,c3,c4,c5, t0,t1,t2,t3,t4,t5;
        LOAD6(c0,c1,c2,c3,c4,c5, xv);
        const int NBK = HW/8;
        int blk = 0;
        bool col = false;
        unsigned mask = __activemask();
        // Phase A: two-state blocks, warp-uniform early exit.
        while (blk < NBK) {
            LOAD6(t0,t1,t2,t3,t4,t5, xv + 6*(blk+1));   // blk+1==NBK reads main chunk: valid
            BLOCK8(OP_TWO);
            c0=t0;c1=t1;c2=t2;c3=t3;c4=t4;c5=t5;
            ++blk;
            col = (lo0==hi0)&&(lo1==hi1)&&(lo2==hi2);
            if (__all_sync(mask, col)) break;
        }
        // Phase B: remaining warmup single-state.
        while (blk < NBK) {
            LOAD6(t0,t1,t2,t3,t4,t5, xv + 6*(blk+1));
            BLOCK8(OP_ONE);
            c0=t0;c1=t1;c2=t2;c3=t3;c4=t4;c5=t5;
            ++blk;
        }
        if (!col) fail = 1;
        n0=lo0; n1=lo1; n2=lo2;
    }
    g_chunk_fail[c] = fail;

    // Main: produce LCH outputs with double-buffered float4 streaming.
    long rem = (long)nB - start;
    if (rem >= LCH) {
        const float4* xv = (const float4*)(x + 3*start);
        float4* ov = (float4*)(out + start);
        float4 c0,c1,c2,c3,c4,c5, t0,t1,t2,t3,t4,t5;
        LOAD6(c0,c1,c2,c3,c4,c5, xv);
        const int MBK = LCH/8;
        #pragma unroll
        for (int blk = 0; blk < MBK; ++blk) {
            if (blk+1 < MBK) LOAD6(t0,t1,t2,t3,t4,t5, xv + 6*(blk+1));
            float p0,p1,p2,p3,p4,p5,p6,p7;
            BLOCK8(OP_MAIN);
            ov[2*blk]   = make_float4(p0,p1,p2,p3);
            ov[2*blk+1] = make_float4(p4,p5,p6,p7);
            c0=t0;c1=t1;c2=t2;c3=t3;c4=t4;c5=t5;
        }
    } else {
        const float* xp = x + 3*start;
        for (int j = 0; j < (int)rem; ++j) {
            float x0=xp[0], x1=xp[1], x2=xp[2]; xp += 3;
            float pd; MAINSTEP(x0,x1,x2,pd);
            out[start + j] = pd;
        }
    }
}

// Rare path: chunks whose bounds failed to collapse redo with HW2 warmup.
__global__ void fixup_kernel(const float* __restrict__ x, const float* __restrict__ W,
                             const float* __restrict__ b, const float* __restrict__ net0,
                             float* __restrict__ out, int nchunk, int nB)
{
    int c = blockIdx.x * blockDim.x + threadIdx.x;
    if (c >= nchunk) return;
    if (!g_chunk_fail[c]) return;
    long start = (long)c * LCH;

    LOADW
    long hw = start < HW2 ? start : HW2;
    const float* xp = x + 3*(start - hw);
    float lo0=0.f,lo1=0.f,lo2=0.f,hi0=1.f,hi1=1.f,hi2=1.f;
    bool col = false;
    for (long s = 0; s < hw; ++s) {
        float x0=xp[0], x1=xp[1], x2=xp[2]; xp += 3;
        MAKEV(x0,x1,x2)
        lo0=sg(lo0,v0); lo1=sg(lo1,v1); lo2=sg(lo2,v2);
        if (!col) {
            hi0=sg(hi0,v0); hi1=sg(hi1,v1); hi2=sg(hi2,v2);
            col = (lo0==hi0)&&(lo1==hi1)&&(lo2==hi2);
        }
    }
    if (!col && start > 0) atomicOr(&g_fail2, 1);
    float n0=lo0, n1=lo1, n2=lo2;
    if (start == 0) { n0=__ldg(net0+0); n1=__ldg(net0+1); n2=__ldg(net0+2); }
    long L = (start + LCH <= nB) ? LCH : (nB - start);
    for (long j = 0; j < L; ++j) {
        float x0=xp[0], x1=xp[1], x2=xp[2]; xp += 3;
        float pd; MAINSTEP(x0,x1,x2,pd);
        out[start + j] = pd;
    }
}

// Ultimate fallback: full serial scan (only if fixup also failed to collapse).
__global__ void fallback_kernel(const float* __restrict__ x, const float* __restrict__ W,
                                const float* __restrict__ b, const float* __restrict__ net0,
                                float* __restrict__ out, int nB)
{
    if (g_fail2 == 0) return;
    if (threadIdx.x != 0 || blockIdx.x != 0) return;
    LOADW
    float n0=__ldg(net0+0), n1=__ldg(net0+1), n2=__ldg(net0+2);
    const float* xp = x;
    for (int i = 0; i < nB; ++i) {
        float x0=xp[0], x1=xp[1], x2=xp[2]; xp += 3;
        float pd; MAINSTEP(x0,x1,x2,pd);
        out[i] = pd;
    }
}

extern "C" void kernel_launch(void* const* d_in, const int* in_sizes, int n_in,
                              void* d_out, int out_size)
{
    const float *x = 0, *W = 0, *b = 0, *n0p = 0;
    long nB = out_size;
    for (int i = 0; i < n_in; ++i) {
        long sz = in_sizes[i];
        if (sz == 3 * nB)      x = (const float*)d_in[i];
        else if (sz == 9)      W = (const float*)d_in[i];
        else if (sz == 3) {
            if (!b) b = (const float*)d_in[i];
            else    n0p = (const float*)d_in[i];
        }
    }
    float* out = (float*)d_out;

    int nchunk = (int)((nB + LCH - 1) / LCH);
    if (nchunk > 65536) nchunk = 65536;   // g_chunk_fail capacity; B=4M -> exactly 65536
    int blocks = (nchunk + TPB - 1) / TPB;

    scan_chunks<<<blocks, TPB>>>(x, W, b, n0p, out, nchunk, (int)nB);
    fixup_kernel<<<(nchunk + 255)/256, 256>>>(x, W, b, n0p, out, nchunk, (int)nB);
    fallback_kernel<<<1, 1>>>(x, W, b, n0p, out, (int)nB);
}

// round 6
// speedup vs baseline: 6.1125x; 1.6208x over previous
#include <cuda_runtime.h>

// 4M-step sequential sigmoid recurrence via saturation-collapse chunking.
// Warp-autonomous design: each warp owns 32 chunks; its contiguous 33-chunk
// span (incl. warmup source rows) is staged into padded smem with cp.async
// (fully coalesced), computed from smem (conflict-free LDS.128), preds written
// back in place, then stored with coalesced STG.128.
// Ladder: per-chunk fail flag -> fixup (HW2 warmup) -> serial fallback.

#define LCH   64                 // steps per chunk
#define HW    48                 // warmup steps (6 pieces of 8)
#define HW2   512                // fixup warmup
#define CHW   32                 // chunks per warp
#define WPB   2                  // warps per block
#define TPB   (WPB*32)
#define ROWB  784                // padded row bytes (768 data + 16) -> stride/16=49 odd
#define NROW  (CHW+1)            // 33 rows (row 0 = previous chunk)
#define SPANB (NROW*ROWB)        // 25872 B per warp
#define NF4   (NROW*48)          // 1584 float4 per span
#define CL    (-14.42695040888963f)   // -10*log2(e)

__device__ unsigned char g_chunk_fail[65536];
__device__ int g_fail2;

__device__ __forceinline__ float ex2a(float t){ float r; asm("ex2.approx.ftz.f32 %0, %1;" : "=f"(r) : "f"(t)); return r; }
__device__ __forceinline__ float rcpa(float t){ float r; asm("rcp.approx.ftz.f32 %0, %1;" : "=f"(r) : "f"(t)); return r; }
__device__ __forceinline__ float sg(float n, float v){ return rcpa(1.0f + ex2a(fmaf(CL, n, v))); }

#define MAKEV(x0,x1,x2) \
    float v0 = fmaf(cw00,(x0), fmaf(cw01,(x1), fmaf(cw02,(x2), cb0))); \
    float v1 = fmaf(cw10,(x0), fmaf(cw11,(x1), fmaf(cw12,(x2), cb1))); \
    float v2 = fmaf(cw20,(x0), fmaf(cw21,(x1), fmaf(cw22,(x2), cb2)));

#define LOADW \
    const float cb0 = CL*(__ldg(b+0)-0.5f), cb1 = CL*(__ldg(b+1)-0.5f), cb2 = CL*(__ldg(b+2)-0.5f); \
    const float cw00=CL*__ldg(W+0), cw01=CL*__ldg(W+1), cw02=CL*__ldg(W+2); \
    const float cw10=CL*__ldg(W+3), cw11=CL*__ldg(W+4), cw12=CL*__ldg(W+5); \
    const float cw20=CL*__ldg(W+6), cw21=CL*__ldg(W+7), cw22=CL*__ldg(W+8);

#define TWOSTEP(x0,x1,x2) do { \
    MAKEV(x0,x1,x2) \
    lo0=sg(lo0,v0); lo1=sg(lo1,v1); lo2=sg(lo2,v2); \
    hi0=sg(hi0,v0); hi1=sg(hi1,v1); hi2=sg(hi2,v2); } while(0)

#define ONESTEPW(x0,x1,x2) do { \
    MAKEV(x0,x1,x2) \
    lo0=sg(lo0,v0); lo1=sg(lo1,v1); lo2=sg(lo2,v2); } while(0)

#define MAINSTEP(x0,x1,x2,pd) do { \
    MAKEV(x0,x1,x2) \
    n0=sg(n0,v0); n1=sg(n1,v1); n2=sg(n2,v2); \
    pd = fmaf((x0),n0, fmaf((x1),n1, (x2)*n2)); } while(0)

#define BLOCK8(OP) do { \
    OP(c0.x,c0.y,c0.z,0); OP(c0.w,c1.x,c1.y,1); \
    OP(c1.z,c1.w,c2.x,2); OP(c2.y,c2.z,c2.w,3); \
    OP(c3.x,c3.y,c3.z,4); OP(c3.w,c4.x,c4.y,5); \
    OP(c4.z,c4.w,c5.x,6); OP(c5.y,c5.z,c5.w,7); } while(0)

#define OP_TWO(x0,x1,x2,j)  TWOSTEP(x0,x1,x2)
#define OP_ONE(x0,x1,x2,j)  ONESTEPW(x0,x1,x2)
#define OP_MAIN(x0,x1,x2,j) MAINSTEP(x0,x1,x2,p##j)

__global__ void __launch_bounds__(TPB)
scan_warp(const float* __restrict__ x, const float* __restrict__ W,
          const float* __restrict__ b, const float* __restrict__ net0,
          float* __restrict__ out)
{
    extern __shared__ char smem_raw[];
    const int w    = threadIdx.x >> 5;
    const int lane = threadIdx.x & 31;
    const long warpid = (long)blockIdx.x * WPB + w;
    const long wc0 = warpid * CHW;            // first chunk owned by this warp
    char* sw = smem_raw + w * SPANB;
    unsigned sb;
    asm("{ .reg .u64 t; cvta.to.shared.u64 t, %1; cvt.u32.u64 %0, t; }" : "=r"(sb) : "l"(sw));

    if (wc0 == 0 && lane == 0) g_fail2 = 0;

    // ---- stage span: chunks [wc0-1, wc0+32), 33 rows x 768B -> padded 784B rows ----
    const char* gbase = (const char*)x + (wc0 - 1) * 768L;
    const bool e0 = (wc0 == 0);
    #pragma unroll
    for (int k = 0; k < (NF4 + 31) / 32; ++k) {
        int idx = k * 32 + lane;
        if (idx < NF4) {
            int r = idx / 48, o = idx - r * 48;
            unsigned dst = sb + r * ROWB + o * 16;
            const char* src = gbase + (long)idx * 16;
            int sz = 16;
            if (e0 && idx < 48) { src = (const char*)x; sz = 0; }   // zero-fill row 0
            asm volatile("cp.async.cg.shared.global [%0], [%1], 16, %2;"
                         :: "r"(dst), "l"(src), "r"(sz));
        }
    }
    asm volatile("cp.async.commit_group;" ::: "memory");

    LOADW   // overlap weight loads with the copy

    asm volatile("cp.async.wait_group 0;" ::: "memory");
    __syncwarp();

    // ---- warmup: lane t reads row t (= chunk c-1), pieces 2..7 (steps 16..64) ----
    float lo0=0.f, lo1=0.f, lo2=0.f, hi0=1.f, hi1=1.f, hi2=1.f;
    const char* wrow = sw + lane * ROWB;
    int p = 2;
    bool col = false;
    while (p < 8) {
        const float4* pc = (const float4*)(wrow + p * 96);
        float4 c0=pc[0], c1=pc[1], c2=pc[2], c3=pc[3], c4=pc[4], c5=pc[5];
        BLOCK8(OP_TWO);
        ++p;
        col = (lo0==hi0) && (lo1==hi1) && (lo2==hi2);
        if (__all_sync(0xffffffffu, col)) break;
    }
    while (p < 8) {
        const float4* pc = (const float4*)(wrow + p * 96);
        float4 c0=pc[0], c1=pc[1], c2=pc[2], c3=pc[3], c4=pc[4], c5=pc[5];
        BLOCK8(OP_ONE);
        ++p;
    }
    float n0 = lo0, n1 = lo1, n2 = lo2;
    unsigned char fail = col ? 0 : 1;
    const long c = wc0 + lane;
    if (c == 0) { n0=__ldg(net0+0); n1=__ldg(net0+1); n2=__ldg(net0+2); fail = 0; }
    g_chunk_fail[c] = fail;
    __syncwarp();   // all warmup reads of rows 1..31 done before preds overwrite them

    // ---- main: lane t reads row t+1 (= chunk c), preds overwrite consumed pieces ----
    char* mrow = sw + (lane + 1) * ROWB;
    #pragma unroll
    for (int j = 0; j < 8; ++j) {
        const float4* pc = (const float4*)(mrow + j * 96);
        float4 c0=pc[0], c1=pc[1], c2=pc[2], c3=pc[3], c4=pc[4], c5=pc[5];
        float p0,p1,p2,p3,p4,p5,p6,p7;
        BLOCK8(OP_MAIN);
        float4* pw = (float4*)(mrow + j * 96);
        pw[0] = make_float4(p0,p1,p2,p3);
        pw[1] = make_float4(p4,p5,p6,p7);
    }
    __syncwarp();   // preds visible warp-wide before cross-lane gather

    // ---- coalesced output: 512 float4 = 32 chunks x 16 float4 ----
    float4* o4 = (float4*)out + wc0 * 16;
    #pragma unroll
    for (int k = 0; k < 16; ++k) {
        int f = k * 32 + lane;            // 0..511
        int cl  = f >> 4;                 // local chunk
        int rem = f & 15;
        const float4* srcv = (const float4*)(sw + (cl + 1) * ROWB + (rem >> 1) * 96 + (rem & 1) * 16);
        o4[f] = *srcv;
    }
}

// Rare path: chunks whose bounds failed to collapse redo with HW2 warmup.
__global__ void fixup_kernel(const float* __restrict__ x, const float* __restrict__ W,
                             const float* __restrict__ b, const float* __restrict__ net0,
                             float* __restrict__ out, int nchunk, int nB)
{
    int c = blockIdx.x * blockDim.x + threadIdx.x;
    if (c >= nchunk) return;
    if (!g_chunk_fail[c]) return;
    long start = (long)c * LCH;

    LOADW
    long hw = start < HW2 ? start : HW2;
    const float* xp = x + 3*(start - hw);
    float lo0=0.f,lo1=0.f,lo2=0.f,hi0=1.f,hi1=1.f,hi2=1.f;
    bool col = false;
    for (long s = 0; s < hw; ++s) {
        float x0=xp[0], x1=xp[1], x2=xp[2]; xp += 3;
        MAKEV(x0,x1,x2)
        lo0=sg(lo0,v0); lo1=sg(lo1,v1); lo2=sg(lo2,v2);
        if (!col) {
            hi0=sg(hi0,v0); hi1=sg(hi1,v1); hi2=sg(hi2,v2);
            col = (lo0==hi0)&&(lo1==hi1)&&(lo2==hi2);
        }
    }
    if (!col && start > 0) atomicOr(&g_fail2, 1);
    float n0=lo0, n1=lo1, n2=lo2;
    if (start == 0) { n0=__ldg(net0+0); n1=__ldg(net0+1); n2=__ldg(net0+2); }
    long L = (start + LCH <= nB) ? LCH : (nB - start);
    for (long j = 0; j < L; ++j) {
        float x0=xp[0], x1=xp[1], x2=xp[2]; xp += 3;
        float pd; MAINSTEP(x0,x1,x2,pd);
        out[start + j] = pd;
    }
}

// Generic tail for shapes not covered by full warps (not hit for B=4M).
__global__ void edge_kernel(const float* __restrict__ x, const float* __restrict__ W,
                            const float* __restrict__ b, const float* __restrict__ net0,
                            float* __restrict__ out, long firstStep, int nB)
{
    long idx = blockIdx.x * blockDim.x + threadIdx.x;
    long start = firstStep + idx * LCH;
    if (start >= nB) return;
    LOADW
    long hw = start < HW2 ? start : HW2;
    const float* xp = x + 3*(start - hw);
    float lo0=0.f,lo1=0.f,lo2=0.f,hi0=1.f,hi1=1.f,hi2=1.f;
    bool col = false;
    for (long s = 0; s < hw; ++s) {
        float x0=xp[0], x1=xp[1], x2=xp[2]; xp += 3;
        MAKEV(x0,x1,x2)
        lo0=sg(lo0,v0); lo1=sg(lo1,v1); lo2=sg(lo2,v2);
        if (!col) {
            hi0=sg(hi0,v0); hi1=sg(hi1,v1); hi2=sg(hi2,v2);
            col = (lo0==hi0)&&(lo1==hi1)&&(lo2==hi2);
        }
    }
    if (!col && start > 0) atomicOr(&g_fail2, 1);
    float n0=lo0, n1=lo1, n2=lo2;
    if (start == 0) { n0=__ldg(net0+0); n1=__ldg(net0+1); n2=__ldg(net0+2); }
    long L = (start + LCH <= nB) ? LCH : (nB - start);
    for (long j = 0; j < L; ++j) {
        float x0=xp[0], x1=xp[1], x2=xp[2]; xp += 3;
        float pd; MAINSTEP(x0,x1,x2,pd);
        out[start + j] = pd;
    }
}

// Ultimate fallback: full serial scan (only if fixup/edge failed to collapse).
__global__ void fallback_kernel(const float* __restrict__ x, const float* __restrict__ W,
                                const float* __restrict__ b, const float* __restrict__ net0,
                                float* __restrict__ out, int nB)
{
    if (g_fail2 == 0) return;
    if (threadIdx.x != 0 || blockIdx.x != 0) return;
    LOADW
    float n0=__ldg(net0+0), n1=__ldg(net0+1), n2=__ldg(net0+2);
    const float* xp = x;
    for (int i = 0; i < nB; ++i) {
        float x0=xp[0], x1=xp[1], x2=xp[2]; xp += 3;
        float pd; MAINSTEP(x0,x1,x2,pd);
        out[i] = pd;
    }
}

extern "C" void kernel_launch(void* const* d_in, const int* in_sizes, int n_in,
                              void* d_out, int out_size)
{
    const float *x = 0, *W = 0, *b = 0, *n0p = 0;
    long nB = out_size;
    for (int i = 0; i < n_in; ++i) {
        long sz = in_sizes[i];
        if (sz == 3 * nB)      x = (const float*)d_in[i];
        else if (sz == 9)      W = (const float*)d_in[i];
        else if (sz == 3) {
            if (!b) b = (const float*)d_in[i];
            else    n0p = (const float*)d_in[i];
        }
    }
    float* out = (float*)d_out;

    long nch   = nB / LCH;                 // full chunks
    long nwarp = nch / CHW;                // full warps of 32 chunks
    long nblk  = nwarp / WPB;              // full blocks
    long ncov  = nblk * WPB * CHW;         // chunks covered by scan_warp
    if (ncov > 65536) { nblk = 65536 / (WPB*CHW); ncov = 65536; }  // flag capacity
    long firstEdge = ncov * LCH;

    size_t smem = (size_t)WPB * SPANB;     // 51744 B
    cudaFuncSetAttribute(scan_warp, cudaFuncAttributeMaxDynamicSharedMemorySize, (int)smem);

    if (nblk > 0)
        scan_warp<<<(int)nblk, TPB, smem>>>(x, W, b, n0p, out);
    if (ncov > 0)
        fixup_kernel<<<(int)((ncov + 255)/256), 256>>>(x, W, b, n0p, out, (int)ncov, (int)nB);
    if (firstEdge < nB) {
        long nEdge = (nB - firstEdge + LCH - 1) / LCH;
        edge_kernel<<<(int)((nEdge + 127)/128), 128>>>(x, W, b, n0p, out, firstEdge, (int)nB);
    }
    fallback_kernel<<<1, 1>>>(x, W, b, n0p, out, (int)nB);
}

// round 7
// speedup vs baseline: 6.3968x; 1.0465x over previous
#include <cuda_runtime.h>

// 4M-step sequential sigmoid recurrence via saturation-collapse chunking.
// Warp-autonomous: each warp owns 32 chunks (one per lane); its contiguous
// 33-row span is staged into padded smem with cp.async (coalesced), computed
// from smem, preds written back in place, stored with coalesced STG.128.
// Sigmoid via single-MUFU tanh.approx: sig(10t) = 0.5*tanh(5t)+0.5.
// Ladder: per-chunk fail flag -> fixup (HW2 warmup) -> serial fallback.

#define LCH   64                 // steps per chunk
#define HW    48                 // warmup steps (pieces 2..7 of previous row)
#define HW2   512                // fixup warmup
#define CHW   32                 // chunks per warp (one per lane)
#define WPB   2                  // warps per block
#define TPB   (WPB*32)
#define ROWB  784                // padded row bytes (768 data + 16), stride/16 odd
#define NROW  (CHW+1)            // 33 rows (row 0 = previous chunk)
#define SPANB (NROW*ROWB)        // 25872 B per warp
#define NF4   (NROW*48)          // 1584 float4 per span
#define C5    (5.0f)             // gain/2

__device__ unsigned char g_chunk_fail[65536];
__device__ int g_fail2;

__device__ __forceinline__ float tanha(float t){ float r; asm("tanh.approx.f32 %0, %1;" : "=f"(r) : "f"(t)); return r; }
// n' = sigmoid(10*(n+u-0.5)) = 0.5*tanh(5n + v) + 0.5,  v = 5*(u-0.5)
__device__ __forceinline__ float sg(float n, float v){
    return fmaf(0.5f, tanha(fmaf(C5, n, v)), 0.5f);
}

#define MAKEV(x0,x1,x2) \
    float v0 = fmaf(cw00,(x0), fmaf(cw01,(x1), fmaf(cw02,(x2), cb0))); \
    float v1 = fmaf(cw10,(x0), fmaf(cw11,(x1), fmaf(cw12,(x2), cb1))); \
    float v2 = fmaf(cw20,(x0), fmaf(cw21,(x1), fmaf(cw22,(x2), cb2)));

#define LOADW \
    const float cb0 = C5*(__ldg(b+0)-0.5f), cb1 = C5*(__ldg(b+1)-0.5f), cb2 = C5*(__ldg(b+2)-0.5f); \
    const float cw00=C5*__ldg(W+0), cw01=C5*__ldg(W+1), cw02=C5*__ldg(W+2); \
    const float cw10=C5*__ldg(W+3), cw11=C5*__ldg(W+4), cw12=C5*__ldg(W+5); \
    const float cw20=C5*__ldg(W+6), cw21=C5*__ldg(W+7), cw22=C5*__ldg(W+8);

#define TWOSTEP(x0,x1,x2) do { \
    MAKEV(x0,x1,x2) \
    lo0=sg(lo0,v0); lo1=sg(lo1,v1); lo2=sg(lo2,v2); \
    hi0=sg(hi0,v0); hi1=sg(hi1,v1); hi2=sg(hi2,v2); } while(0)

#define ONESTEPW(x0,x1,x2) do { \
    MAKEV(x0,x1,x2) \
    lo0=sg(lo0,v0); lo1=sg(lo1,v1); lo2=sg(lo2,v2); } while(0)

#define MAINSTEP(x0,x1,x2,pd) do { \
    MAKEV(x0,x1,x2) \
    n0=sg(n0,v0); n1=sg(n1,v1); n2=sg(n2,v2); \
    pd = fmaf((x0),n0, fmaf((x1),n1, (x2)*n2)); } while(0)

#define BLOCK8(OP) do { \
    OP(c0.x,c0.y,c0.z,0); OP(c0.w,c1.x,c1.y,1); \
    OP(c1.z,c1.w,c2.x,2); OP(c2.y,c2.z,c2.w,3); \
    OP(c3.x,c3.y,c3.z,4); OP(c3.w,c4.x,c4.y,5); \
    OP(c4.z,c4.w,c5.x,6); OP(c5.y,c5.z,c5.w,7); } while(0)

#define OP_TWO(x0,x1,x2,j)  TWOSTEP(x0,x1,x2)
#define OP_ONE(x0,x1,x2,j)  ONESTEPW(x0,x1,x2)
#define OP_MAIN(x0,x1,x2,j) MAINSTEP(x0,x1,x2,p##j)

__global__ void __launch_bounds__(TPB)
scan_warp(const float* __restrict__ x, const float* __restrict__ W,
          const float* __restrict__ b, const float* __restrict__ net0,
          float* __restrict__ out)
{
    extern __shared__ char smem_raw[];
    const int w    = threadIdx.x >> 5;
    const int lane = threadIdx.x & 31;
    const long warpid = (long)blockIdx.x * WPB + w;
    const long wc0 = warpid * CHW;            // first chunk owned by this warp
    char* sw = smem_raw + w * SPANB;
    unsigned sb;
    asm("{ .reg .u64 t; cvta.to.shared.u64 t, %1; cvt.u32.u64 %0, t; }" : "=r"(sb) : "l"(sw));

    if (wc0 == 0 && lane == 0) g_fail2 = 0;

    // ---- stage span: chunks [wc0-1, wc0+32), 33 rows x 768B -> padded 784B rows ----
    const char* gbase = (const char*)x + (wc0 - 1) * 768L;
    const bool e0 = (wc0 == 0);
    #pragma unroll
    for (int k = 0; k < (NF4 + 31) / 32; ++k) {
        int idx = k * 32 + lane;
        if (idx < NF4) {
            int r = idx / 48, o = idx - r * 48;
            unsigned dst = sb + r * ROWB + o * 16;
            const char* src = gbase + (long)idx * 16;
            int sz = 16;
            if (e0 && idx < 48) { src = (const char*)x; sz = 0; }   // zero-fill row 0
            asm volatile("cp.async.cg.shared.global [%0], [%1], 16, %2;"
                         :: "r"(dst), "l"(src), "r"(sz));
        }
    }
    asm volatile("cp.async.commit_group;" ::: "memory");

    LOADW   // overlap weight loads with the copy

    asm volatile("cp.async.wait_group 0;" ::: "memory");
    __syncwarp();

    // ---- warmup: lane t reads row t (= chunk c-1), pieces 2..7 (steps 16..64) ----
    float lo0=0.f, lo1=0.f, lo2=0.f, hi0=1.f, hi1=1.f, hi2=1.f;
    const char* wrow = sw + lane * ROWB;
    int p = 2;
    bool col = false;
    while (p < 8) {
        const float4* pc = (const float4*)(wrow + p * 96);
        float4 c0=pc[0], c1=pc[1], c2=pc[2], c3=pc[3], c4=pc[4], c5=pc[5];
        BLOCK8(OP_TWO);
        ++p;
        col = (lo0==hi0) && (lo1==hi1) && (lo2==hi2);
        if (__all_sync(0xffffffffu, col)) break;
    }
    while (p < 8) {
        const float4* pc = (const float4*)(wrow + p * 96);
        float4 c0=pc[0], c1=pc[1], c2=pc[2], c3=pc[3], c4=pc[4], c5=pc[5];
        BLOCK8(OP_ONE);
        ++p;
    }
    float n0 = lo0, n1 = lo1, n2 = lo2;
    unsigned char fail = col ? 0 : 1;
    const long c = wc0 + lane;
    if (c == 0) { n0=__ldg(net0+0); n1=__ldg(net0+1); n2=__ldg(net0+2); fail = 0; }
    g_chunk_fail[c] = fail;
    __syncwarp();   // all warmup reads of rows 0..31 done before preds overwrite

    // ---- main: lane t reads row t+1 (= chunk c), preds overwrite consumed pieces ----
    char* mrow = sw + (lane + 1) * ROWB;
    #pragma unroll
    for (int j = 0; j < 8; ++j) {
        const float4* pc = (const float4*)(mrow + j * 96);
        float4 c0=pc[0], c1=pc[1], c2=pc[2], c3=pc[3], c4=pc[4], c5=pc[5];
        float p0,p1,p2,p3,p4,p5,p6,p7;
        BLOCK8(OP_MAIN);
        float4* pw = (float4*)(mrow + j * 96);
        pw[0] = make_float4(p0,p1,p2,p3);
        pw[1] = make_float4(p4,p5,p6,p7);
    }
    __syncwarp();   // preds visible warp-wide before cross-lane gather

    // ---- coalesced output: 512 float4 = 32 chunks x 16 float4 ----
    float4* o4 = (float4*)out + wc0 * 16;
    #pragma unroll
    for (int k = 0; k < 16; ++k) {
        int f = k * 32 + lane;            // 0..511
        int cl  = f >> 4;                 // local chunk
        int rem = f & 15;
        const float4* srcv = (const float4*)(sw + (cl + 1) * ROWB + (rem >> 1) * 96 + (rem & 1) * 16);
        o4[f] = *srcv;
    }
}

// Rare path: chunks whose bounds failed to collapse redo with HW2 warmup.
__global__ void fixup_kernel(const float* __restrict__ x, const float* __restrict__ W,
                             const float* __restrict__ b, const float* __restrict__ net0,
                             float* __restrict__ out, int nchunk, int nB)
{
    int c = blockIdx.x * blockDim.x + threadIdx.x;
    if (c >= nchunk) return;
    if (!g_chunk_fail[c]) return;
    long start = (long)c * LCH;

    LOADW
    long hw = start < HW2 ? start : HW2;
    const float* xp = x + 3*(start - hw);
    float lo0=0.f,lo1=0.f,lo2=0.f,hi0=1.f,hi1=1.f,hi2=1.f;
    bool col = false;
    for (long s = 0; s < hw; ++s) {
        float x0=xp[0], x1=xp[1], x2=xp[2]; xp += 3;
        MAKEV(x0,x1,x2)
        lo0=sg(lo0,v0); lo1=sg(lo1,v1); lo2=sg(lo2,v2);
        if (!col) {
            hi0=sg(hi0,v0); hi1=sg(hi1,v1); hi2=sg(hi2,v2);
            col = (lo0==hi0)&&(lo1==hi1)&&(lo2==hi2);
        }
    }
    if (!col && start > 0) atomicOr(&g_fail2, 1);
    float n0=lo0, n1=lo1, n2=lo2;
    if (start == 0) { n0=__ldg(net0+0); n1=__ldg(net0+1); n2=__ldg(net0+2); }
    long L = (start + LCH <= nB) ? LCH : (nB - start);
    for (long j = 0; j < L; ++j) {
        float x0=xp[0], x1=xp[1], x2=xp[2]; xp += 3;
        float pd; MAINSTEP(x0,x1,x2,pd);
        out[start + j] = pd;
    }
}

// Generic tail for shapes not covered by full warps (not hit for B=4M).
__global__ void edge_kernel(const float* __restrict__ x, const float* __restrict__ W,
                            const float* __restrict__ b, const float* __restrict__ net0,
                            float* __restrict__ out, long firstStep, int nB)
{
    long idx = blockIdx.x * blockDim.x + threadIdx.x;
    long start = firstStep + idx * LCH;
    if (start >= nB) return;
    LOADW
    long hw = start < HW2 ? start : HW2;
    const float* xp = x + 3*(start - hw);
    float lo0=0.f,lo1=0.f,lo2=0.f,hi0=1.f,hi1=1.f,hi2=1.f;
    bool col = false;
    for (long s = 0; s < hw; ++s) {
        float x0=xp[0], x1=xp[1], x2=xp[2]; xp += 3;
        MAKEV(x0,x1,x2)
        lo0=sg(lo0,v0); lo1=sg(lo1,v1); lo2=sg(lo2,v2);
        if (!col) {
            hi0=sg(hi0,v0); hi1=sg(hi1,v1); hi2=sg(hi2,v2);
            col = (lo0==hi0)&&(lo1==hi1)&&(lo2==hi2);
        }
    }
    if (!col && start > 0) atomicOr(&g_fail2, 1);
    float n0=lo0, n1=lo1, n2=lo2;
    if (start == 0) { n0=__ldg(net0+0); n1=__ldg(net0+1); n2=__ldg(net0+2); }
    long L = (start + LCH <= nB) ? LCH : (nB - start);
    for (long j = 0; j < L; ++j) {
        float x0=xp[0], x1=xp[1], x2=xp[2]; xp += 3;
        float pd; MAINSTEP(x0,x1,x2,pd);
        out[start + j] = pd;
    }
}

// Ultimate fallback: full serial scan (only if fixup/edge failed to collapse).
__global__ void fallback_kernel(const float* __restrict__ x, const float* __restrict__ W,
                                const float* __restrict__ b, const float* __restrict__ net0,
                                float* __restrict__ out, int nB)
{
    if (g_fail2 == 0) return;
    if (threadIdx.x != 0 || blockIdx.x != 0) return;
    LOADW
    float n0=__ldg(net0+0), n1=__ldg(net0+1), n2=__ldg(net0+2);
    const float* xp = x;
    for (int i = 0; i < nB; ++i) {
        float x0=xp[0], x1=xp[1], x2=xp[2]; xp += 3;
        float pd; MAINSTEP(x0,x1,x2,pd);
        out[i] = pd;
    }
}

extern "C" void kernel_launch(void* const* d_in, const int* in_sizes, int n_in,
                              void* d_out, int out_size)
{
    const float *x = 0, *W = 0, *b = 0, *n0p = 0;
    long nB = out_size;
    for (int i = 0; i < n_in; ++i) {
        long sz = in_sizes[i];
        if (sz == 3 * nB)      x = (const float*)d_in[i];
        else if (sz == 9)      W = (const float*)d_in[i];
        else if (sz == 3) {
            if (!b) b = (const float*)d_in[i];
            else    n0p = (const float*)d_in[i];
        }
    }
    float* out = (float*)d_out;

    long nch   = nB / LCH;                 // full chunks
    long nwarp = nch / CHW;                // full warps of 32 chunks
    long nblk  = nwarp / WPB;              // full blocks
    long ncov  = nblk * WPB * CHW;         // chunks covered by scan_warp
    if (ncov > 65536) { nblk = 65536 / (WPB*CHW); ncov = 65536; }  // flag capacity
    long firstEdge = ncov * LCH;

    size_t smem = (size_t)WPB * SPANB;     // 51744 B
    cudaFuncSetAttribute(scan_warp, cudaFuncAttributeMaxDynamicSharedMemorySize, (int)smem);

    if (nblk > 0)
        scan_warp<<<(int)nblk, TPB, smem>>>(x, W, b, n0p, out);
    if (ncov > 0)
        fixup_kernel<<<(int)((ncov + 255)/256), 256>>>(x, W, b, n0p, out, (int)ncov, (int)nB);
    if (firstEdge < nB) {
        long nEdge = (nB - firstEdge + LCH - 1) / LCH;
        edge_kernel<<<(int)((nEdge + 127)/128), 128>>>(x, W, b, n0p, out, firstEdge, (int)nB);
    }
    fallback_kernel<<<1, 1>>>(x, W, b, n0p, out, (int)nB);
}